// round 2
// baseline (speedup 1.0000x reference)
#include <cuda_runtime.h>
#include <cstdint>

// Problem constants
#define BATCH 4
#define DIM   512
#define HEADS 8
#define DHEAD 64
#define HW    4096   // 64*64 query positions
#define LKV   1024   // 32*32 kv positions
#define KVK   2048   // im2col K for the 2x2 stride-2 conv (512*4)

// Scratch (device globals; allocation-free per harness rules)
__device__ float g_q [BATCH * DIM * HW];        // Q  [b][hd][s]   32 MB
__device__ float g_kv[BATCH * 2 * DIM * LKV];   // KV [b][o][ij]   16 MB
__device__ float g_o [BATCH * DIM * HW];        // attn out        32 MB

// ---------------------------------------------------------------------------
// Classic 128x128x8 tiled SGEMM:  C[b] = A @ B[b]
// A: [M,K] row-major (weights, shared across batch)
// B: [K,N] row-major, batched with stride K*N
// C: [M,N] row-major, batched with stride M*N
// 256 threads, 8x8 micro-tile per thread. M,N multiples of 128; K of 8.
// ---------------------------------------------------------------------------
template <int M, int N, int K>
__global__ __launch_bounds__(256)
void sgemm_kernel(const float* __restrict__ A,
                  const float* __restrict__ Bsrc,
                  float* __restrict__ Csrc)
{
    const int b = blockIdx.z;
    const float* Bp = Bsrc + (size_t)b * K * N;
    float*       Cp = Csrc + (size_t)b * M * N;

    __shared__ float As[8][128];
    __shared__ float Bs[8][128];

    const int tid  = threadIdx.x;
    const int tx   = tid & 15;
    const int ty   = tid >> 4;
    const int row0 = blockIdx.y * 128;
    const int col0 = blockIdx.x * 128;

    const int a_row = tid >> 1;          // 0..127
    const int a_col = (tid & 1) * 4;     // 0 or 4
    const int b_row = tid >> 5;          // 0..7
    const int b_col = (tid & 31) * 4;    // 0..124

    float acc[8][8];
#pragma unroll
    for (int i = 0; i < 8; i++)
#pragma unroll
        for (int j = 0; j < 8; j++) acc[i][j] = 0.f;

    for (int k0 = 0; k0 < K; k0 += 8) {
        float4 av = *reinterpret_cast<const float4*>(
            A + (size_t)(row0 + a_row) * K + k0 + a_col);
        As[a_col + 0][a_row] = av.x;
        As[a_col + 1][a_row] = av.y;
        As[a_col + 2][a_row] = av.z;
        As[a_col + 3][a_row] = av.w;
        *reinterpret_cast<float4*>(&Bs[b_row][b_col]) =
            *reinterpret_cast<const float4*>(
                Bp + (size_t)(k0 + b_row) * N + col0 + b_col);
        __syncthreads();

#pragma unroll
        for (int kk = 0; kk < 8; kk++) {
            float4 a0 = *reinterpret_cast<const float4*>(&As[kk][ty * 8]);
            float4 a1 = *reinterpret_cast<const float4*>(&As[kk][ty * 8 + 4]);
            float4 b0 = *reinterpret_cast<const float4*>(&Bs[kk][tx * 8]);
            float4 b1 = *reinterpret_cast<const float4*>(&Bs[kk][tx * 8 + 4]);
            float ar[8] = {a0.x, a0.y, a0.z, a0.w, a1.x, a1.y, a1.z, a1.w};
            float br[8] = {b0.x, b0.y, b0.z, b0.w, b1.x, b1.y, b1.z, b1.w};
#pragma unroll
            for (int i = 0; i < 8; i++)
#pragma unroll
                for (int j = 0; j < 8; j++)
                    acc[i][j] += ar[i] * br[j];
        }
        __syncthreads();
    }

#pragma unroll
    for (int i = 0; i < 8; i++) {
        float* crow = Cp + (size_t)(row0 + ty * 8 + i) * N + col0 + tx * 8;
        *reinterpret_cast<float4*>(crow)     = make_float4(acc[i][0], acc[i][1], acc[i][2], acc[i][3]);
        *reinterpret_cast<float4*>(crow + 4) = make_float4(acc[i][4], acc[i][5], acc[i][6], acc[i][7]);
    }
}

// ---------------------------------------------------------------------------
// KV conv as implicit-im2col GEMM.
// A = wkv flattened [1024][2048], k index = c*4 + p*2 + q (matches OIHW flat).
// B[k][n] = x[b][c][(2i+p)*64 + (2j+q)], n = i*32 + j.
// C = g_kv[b][o][n], M=1024, N=1024, K=2048.
// ---------------------------------------------------------------------------
__global__ __launch_bounds__(256)
void kv_gemm_kernel(const float* __restrict__ Wkv,
                    const float* __restrict__ X,
                    float* __restrict__ KVout)
{
    constexpr int M = 1024, N = 1024, K = 2048;
    const int b = blockIdx.z;
    const float* Xb = X + (size_t)b * DIM * HW;
    float*       Cp = KVout + (size_t)b * M * N;

    __shared__ float As[8][128];
    __shared__ float Bs[8][128];

    const int tid  = threadIdx.x;
    const int tx   = tid & 15;
    const int ty   = tid >> 4;
    const int row0 = blockIdx.y * 128;
    const int col0 = blockIdx.x * 128;

    const int a_row = tid >> 1;
    const int a_col = (tid & 1) * 4;
    const int b_row = tid >> 5;
    const int b_col = (tid & 31) * 4;

    float acc[8][8];
#pragma unroll
    for (int i = 0; i < 8; i++)
#pragma unroll
        for (int j = 0; j < 8; j++) acc[i][j] = 0.f;

    for (int k0 = 0; k0 < K; k0 += 8) {
        float4 av = *reinterpret_cast<const float4*>(
            Wkv + (size_t)(row0 + a_row) * K + k0 + a_col);
        As[a_col + 0][a_row] = av.x;
        As[a_col + 1][a_row] = av.y;
        As[a_col + 2][a_row] = av.z;
        As[a_col + 3][a_row] = av.w;

        {
            const int krow = k0 + b_row;         // 0..2047
            const int c  = krow >> 2;
            const int p  = (krow >> 1) & 1;
            const int qq = krow & 1;
            const float* xr = Xb + (size_t)c * HW + p * 64 + qq;
#pragma unroll
            for (int u = 0; u < 4; u++) {
                const int n  = col0 + b_col + u; // 0..1023
                const int ii = n >> 5;
                const int jj = n & 31;
                Bs[b_row][b_col + u] = xr[ii * 128 + jj * 2];
            }
        }
        __syncthreads();

#pragma unroll
        for (int kk = 0; kk < 8; kk++) {
            float4 a0 = *reinterpret_cast<const float4*>(&As[kk][ty * 8]);
            float4 a1 = *reinterpret_cast<const float4*>(&As[kk][ty * 8 + 4]);
            float4 b0 = *reinterpret_cast<const float4*>(&Bs[kk][tx * 8]);
            float4 b1 = *reinterpret_cast<const float4*>(&Bs[kk][tx * 8 + 4]);
            float ar[8] = {a0.x, a0.y, a0.z, a0.w, a1.x, a1.y, a1.z, a1.w};
            float br[8] = {b0.x, b0.y, b0.z, b0.w, b1.x, b1.y, b1.z, b1.w};
#pragma unroll
            for (int i = 0; i < 8; i++)
#pragma unroll
                for (int j = 0; j < 8; j++)
                    acc[i][j] += ar[i] * br[j];
        }
        __syncthreads();
    }

#pragma unroll
    for (int i = 0; i < 8; i++) {
        float* crow = Cp + (size_t)(row0 + ty * 8 + i) * N + col0 + tx * 8;
        *reinterpret_cast<float4*>(crow)     = make_float4(acc[i][0], acc[i][1], acc[i][2], acc[i][3]);
        *reinterpret_cast<float4*>(crow + 4) = make_float4(acc[i][4], acc[i][5], acc[i][6], acc[i][7]);
    }
}

// ---------------------------------------------------------------------------
// Fused flash-style attention, fp32.
// Grid: (HW/64, HEADS, BATCH), 64 threads per CTA, one thread = one query row.
// Q stored [b][hd][s] -> per-thread q[64] in registers (coalesced loads).
// K/V tiles (64 cols) staged in padded smem; online softmax with 16-wide
// score sub-chunks to keep register count bounded (q[64]+O[64]+s[16]).
// ---------------------------------------------------------------------------
__global__ __launch_bounds__(64)
void attn_kernel(const float* __restrict__ Q,
                 const float* __restrict__ KV,
                 float* __restrict__ Oout)
{
    const int bb = blockIdx.z;
    const int h  = blockIdx.y;
    const int i0 = blockIdx.x * 64;
    const int t  = threadIdx.x;

    const float* Qb = Q  + ((size_t)bb * DIM + h * DHEAD) * HW;
    const float* Kb = KV + ((size_t)bb * 2 * DIM + h * DHEAD) * LKV;
    const float* Vb = KV + ((size_t)bb * 2 * DIM + DIM + h * DHEAD) * LKV;
    float*       Ob = Oout + ((size_t)bb * DIM + h * DHEAD) * HW;

    __shared__ float Ks[64][65];
    __shared__ float Vs[64][65];

    float q[64], O[64];
#pragma unroll
    for (int dd = 0; dd < 64; dd++) {
        q[dd] = Qb[(size_t)dd * HW + i0 + t] * 0.125f;   // fold scale=d^-0.5
        O[dd] = 0.f;
    }

    float m = -1e30f, l = 0.f;

    for (int j0 = 0; j0 < LKV; j0 += 64) {
        __syncthreads();
#pragma unroll
        for (int dd = 0; dd < 64; dd++) {
            Ks[dd][t] = Kb[(size_t)dd * LKV + j0 + t];
            Vs[dd][t] = Vb[(size_t)dd * LKV + j0 + t];
        }
        __syncthreads();

#pragma unroll
        for (int sub = 0; sub < 4; sub++) {
            float s[16];
            float smax = -1e30f;
#pragma unroll
            for (int jj = 0; jj < 16; jj++) {
                float acc = 0.f;
#pragma unroll
                for (int dd = 0; dd < 64; dd++)
                    acc += q[dd] * Ks[dd][sub * 16 + jj];
                s[jj] = acc;
                smax  = fmaxf(smax, acc);
            }
            if (smax > m) {
                const float f = __expf(m - smax);
                m = smax;
                l *= f;
#pragma unroll
                for (int dd = 0; dd < 64; dd++) O[dd] *= f;
            }
#pragma unroll
            for (int jj = 0; jj < 16; jj++) {
                const float p = __expf(s[jj] - m);
                l += p;
#pragma unroll
                for (int dd = 0; dd < 64; dd++)
                    O[dd] += p * Vs[dd][sub * 16 + jj];
            }
        }
    }

    const float inv = 1.f / l;
#pragma unroll
    for (int dd = 0; dd < 64; dd++)
        Ob[(size_t)dd * HW + i0 + t] = O[dd] * inv;
}

// ---------------------------------------------------------------------------
// Launch
// ---------------------------------------------------------------------------
extern "C" void kernel_launch(void* const* d_in, const int* in_sizes, int n_in,
                              void* d_out, int out_size)
{
    const float* x    = (const float*)d_in[0];   // [4,512,64,64]
    const float* wq   = (const float*)d_in[1];   // [512,512,1,1]
    const float* wkv  = (const float*)d_in[2];   // [1024,512,2,2]
    const float* wout = (const float*)d_in[3];   // [512,512,1,1]
    float* out = (float*)d_out;                  // [4,512,64,64]

    float *qbuf, *kvbuf, *obuf;
    cudaGetSymbolAddress((void**)&qbuf,  g_q);
    cudaGetSymbolAddress((void**)&kvbuf, g_kv);
    cudaGetSymbolAddress((void**)&obuf,  g_o);

    // Q = Wq @ X   : M=512, N=4096, K=512, batched over 4
    sgemm_kernel<512, 4096, 512><<<dim3(32, 4, BATCH), 256>>>(wq, x, qbuf);

    // KV = Wkv @ im2col(X) : M=1024, N=1024, K=2048
    kv_gemm_kernel<<<dim3(8, 8, BATCH), 256>>>(wkv, x, kvbuf);

    // Fused attention
    attn_kernel<<<dim3(HW / 64, HEADS, BATCH), 64>>>(qbuf, kvbuf, obuf);

    // Y = Wout @ O
    sgemm_kernel<512, 4096, 512><<<dim3(32, 4, BATCH), 256>>>(wout, obuf, out);
}

// round 3
// speedup vs baseline: 2.0676x; 2.0676x over previous
#include <cuda_runtime.h>
#include <cstdint>

// Problem constants
#define BATCH 4
#define DIM   512
#define HEADS 8
#define DHEAD 64
#define HW    4096   // 64*64 query positions
#define LKV   1024   // 32*32 kv positions

// Scratch (device globals; allocation-free per harness rules)
__device__ float g_q [BATCH * DIM * HW];        // Q  [b][hd][s]
__device__ float g_kv[BATCH * 2 * DIM * LKV];   // KV [b][o][ij]
__device__ float g_o [BATCH * DIM * HW];        // attn out

// ---------------------------------------------------------------------------
// Classic 128x128x8 tiled SGEMM:  C[b] = A @ B[b]   (unchanged, validated)
// ---------------------------------------------------------------------------
template <int M, int N, int K>
__global__ __launch_bounds__(256)
void sgemm_kernel(const float* __restrict__ A,
                  const float* __restrict__ Bsrc,
                  float* __restrict__ Csrc)
{
    const int b = blockIdx.z;
    const float* Bp = Bsrc + (size_t)b * K * N;
    float*       Cp = Csrc + (size_t)b * M * N;

    __shared__ float As[8][128];
    __shared__ float Bs[8][128];

    const int tid  = threadIdx.x;
    const int tx   = tid & 15;
    const int ty   = tid >> 4;
    const int row0 = blockIdx.y * 128;
    const int col0 = blockIdx.x * 128;

    const int a_row = tid >> 1;
    const int a_col = (tid & 1) * 4;
    const int b_row = tid >> 5;
    const int b_col = (tid & 31) * 4;

    float acc[8][8];
#pragma unroll
    for (int i = 0; i < 8; i++)
#pragma unroll
        for (int j = 0; j < 8; j++) acc[i][j] = 0.f;

    for (int k0 = 0; k0 < K; k0 += 8) {
        float4 av = *reinterpret_cast<const float4*>(
            A + (size_t)(row0 + a_row) * K + k0 + a_col);
        As[a_col + 0][a_row] = av.x;
        As[a_col + 1][a_row] = av.y;
        As[a_col + 2][a_row] = av.z;
        As[a_col + 3][a_row] = av.w;
        *reinterpret_cast<float4*>(&Bs[b_row][b_col]) =
            *reinterpret_cast<const float4*>(
                Bp + (size_t)(k0 + b_row) * N + col0 + b_col);
        __syncthreads();

#pragma unroll
        for (int kk = 0; kk < 8; kk++) {
            float4 a0 = *reinterpret_cast<const float4*>(&As[kk][ty * 8]);
            float4 a1 = *reinterpret_cast<const float4*>(&As[kk][ty * 8 + 4]);
            float4 b0 = *reinterpret_cast<const float4*>(&Bs[kk][tx * 8]);
            float4 b1 = *reinterpret_cast<const float4*>(&Bs[kk][tx * 8 + 4]);
            float ar[8] = {a0.x, a0.y, a0.z, a0.w, a1.x, a1.y, a1.z, a1.w};
            float br[8] = {b0.x, b0.y, b0.z, b0.w, b1.x, b1.y, b1.z, b1.w};
#pragma unroll
            for (int i = 0; i < 8; i++)
#pragma unroll
                for (int j = 0; j < 8; j++)
                    acc[i][j] += ar[i] * br[j];
        }
        __syncthreads();
    }

#pragma unroll
    for (int i = 0; i < 8; i++) {
        float* crow = Cp + (size_t)(row0 + ty * 8 + i) * N + col0 + tx * 8;
        *reinterpret_cast<float4*>(crow)     = make_float4(acc[i][0], acc[i][1], acc[i][2], acc[i][3]);
        *reinterpret_cast<float4*>(crow + 4) = make_float4(acc[i][4], acc[i][5], acc[i][6], acc[i][7]);
    }
}

// ---------------------------------------------------------------------------
// KV conv as implicit-im2col GEMM (unchanged, validated)
// ---------------------------------------------------------------------------
__global__ __launch_bounds__(256)
void kv_gemm_kernel(const float* __restrict__ Wkv,
                    const float* __restrict__ X,
                    float* __restrict__ KVout)
{
    constexpr int M = 1024, N = 1024, K = 2048;
    const int b = blockIdx.z;
    const float* Xb = X + (size_t)b * DIM * HW;
    float*       Cp = KVout + (size_t)b * M * N;

    __shared__ float As[8][128];
    __shared__ float Bs[8][128];

    const int tid  = threadIdx.x;
    const int tx   = tid & 15;
    const int ty   = tid >> 4;
    const int row0 = blockIdx.y * 128;
    const int col0 = blockIdx.x * 128;

    const int a_row = tid >> 1;
    const int a_col = (tid & 1) * 4;
    const int b_row = tid >> 5;
    const int b_col = (tid & 31) * 4;

    float acc[8][8];
#pragma unroll
    for (int i = 0; i < 8; i++)
#pragma unroll
        for (int j = 0; j < 8; j++) acc[i][j] = 0.f;

    for (int k0 = 0; k0 < K; k0 += 8) {
        float4 av = *reinterpret_cast<const float4*>(
            Wkv + (size_t)(row0 + a_row) * K + k0 + a_col);
        As[a_col + 0][a_row] = av.x;
        As[a_col + 1][a_row] = av.y;
        As[a_col + 2][a_row] = av.z;
        As[a_col + 3][a_row] = av.w;

        {
            const int krow = k0 + b_row;
            const int c  = krow >> 2;
            const int p  = (krow >> 1) & 1;
            const int qq = krow & 1;
            const float* xr = Xb + (size_t)c * HW + p * 64 + qq;
#pragma unroll
            for (int u = 0; u < 4; u++) {
                const int n  = col0 + b_col + u;
                const int ii = n >> 5;
                const int jj = n & 31;
                Bs[b_row][b_col + u] = xr[ii * 128 + jj * 2];
            }
        }
        __syncthreads();

#pragma unroll
        for (int kk = 0; kk < 8; kk++) {
            float4 a0 = *reinterpret_cast<const float4*>(&As[kk][ty * 8]);
            float4 a1 = *reinterpret_cast<const float4*>(&As[kk][ty * 8 + 4]);
            float4 b0 = *reinterpret_cast<const float4*>(&Bs[kk][tx * 8]);
            float4 b1 = *reinterpret_cast<const float4*>(&Bs[kk][tx * 8 + 4]);
            float ar[8] = {a0.x, a0.y, a0.z, a0.w, a1.x, a1.y, a1.z, a1.w};
            float br[8] = {b0.x, b0.y, b0.z, b0.w, b1.x, b1.y, b1.z, b1.w};
#pragma unroll
            for (int i = 0; i < 8; i++)
#pragma unroll
                for (int j = 0; j < 8; j++)
                    acc[i][j] += ar[i] * br[j];
        }
        __syncthreads();
    }

#pragma unroll
    for (int i = 0; i < 8; i++) {
        float* crow = Cp + (size_t)(row0 + ty * 8 + i) * N + col0 + tx * 8;
        *reinterpret_cast<float4*>(crow)     = make_float4(acc[i][0], acc[i][1], acc[i][2], acc[i][3]);
        *reinterpret_cast<float4*>(crow + 4) = make_float4(acc[i][4], acc[i][5], acc[i][6], acc[i][7]);
    }
}

// ---------------------------------------------------------------------------
// Flash attention, register-blocked GEMM style (NEW).
// CTA = 128 queries x full head. 256 threads as 16(tx) x 16(ty).
// Phase A: S = Q^T K chunk (128x128x64), 8x8 microtile/thread.
// Online softmax: row stats reduced across the 16 tx lanes (half-warp shfl).
// P staged in smem; Phase B: O += P @ V^T (128x64x128), 8x4 microtile/thread,
// V transposed in smem for conflict-free reads.
// Smem: Qs 64x128 | Ks 64x128 | Vt 128x68 | Ps 128x132  = 164 KB dynamic.
// ---------------------------------------------------------------------------
#define ATTN_SMEM ((64*128 + 64*128 + 128*68 + 128*132) * 4)

__global__ __launch_bounds__(256, 1)
void attn_kernel(const float* __restrict__ Q,
                 const float* __restrict__ KV,
                 float* __restrict__ Oout)
{
    const int bb = blockIdx.z;
    const int h  = blockIdx.y;
    const int i0 = blockIdx.x * 128;
    const int tid = threadIdx.x;
    const int tx  = tid & 15;
    const int ty  = tid >> 4;

    const float* Qb = Q  + ((size_t)bb * DIM + h * DHEAD) * HW;
    const float* Kb = KV + ((size_t)bb * 2 * DIM + h * DHEAD) * LKV;
    const float* Vb = KV + ((size_t)bb * 2 * DIM + DIM + h * DHEAD) * LKV;
    float*       Ob = Oout + ((size_t)bb * DIM + h * DHEAD) * HW;

    extern __shared__ float sm[];
    float* Qs = sm;                 // [64][128]
    float* Ks = Qs + 64 * 128;      // [64][128]
    float* Vt = Ks + 64 * 128;      // [128][68]  Vt[j][dd]
    float* Ps = Vt + 128 * 68;      // [128][132]

    // Load Q tile (scaled by d^-0.5 = 0.125)
#pragma unroll
    for (int it = 0; it < 8; it++) {
        int idx = tid * 4 + it * 1024;
        int dd = idx >> 7, ic = idx & 127;
        float4 v = *reinterpret_cast<const float4*>(Qb + (size_t)dd * HW + i0 + ic);
        v.x *= 0.125f; v.y *= 0.125f; v.z *= 0.125f; v.w *= 0.125f;
        *reinterpret_cast<float4*>(Qs + dd * 128 + ic) = v;
    }

    float m[8], l[8], Oacc[8][4];
#pragma unroll
    for (int r = 0; r < 8; r++) {
        m[r] = -1e30f; l[r] = 0.f;
#pragma unroll
        for (int c = 0; c < 4; c++) Oacc[r][c] = 0.f;
    }

    for (int j0 = 0; j0 < LKV; j0 += 128) {
        __syncthreads();  // prev chunk's O-GEMM done -> Ks/Vt/Ps reusable; also covers Q load on iter 0

        // Load K chunk; load V chunk transposed
#pragma unroll
        for (int it = 0; it < 8; it++) {
            int idx = tid * 4 + it * 1024;
            int dd = idx >> 7, jc = idx & 127;
            *reinterpret_cast<float4*>(Ks + dd * 128 + jc) =
                *reinterpret_cast<const float4*>(Kb + (size_t)dd * LKV + j0 + jc);
            float4 v = *reinterpret_cast<const float4*>(Vb + (size_t)dd * LKV + j0 + jc);
            Vt[(jc + 0) * 68 + dd] = v.x;
            Vt[(jc + 1) * 68 + dd] = v.y;
            Vt[(jc + 2) * 68 + dd] = v.z;
            Vt[(jc + 3) * 68 + dd] = v.w;
        }
        __syncthreads();

        // ---- Phase A: S = Q^T K (8x8 per thread) ----
        float s[8][8];
#pragma unroll
        for (int r = 0; r < 8; r++)
#pragma unroll
            for (int c = 0; c < 8; c++) s[r][c] = 0.f;

#pragma unroll 4
        for (int dd = 0; dd < 64; dd++) {
            float4 a0 = *reinterpret_cast<const float4*>(Qs + dd * 128 + ty * 8);
            float4 a1 = *reinterpret_cast<const float4*>(Qs + dd * 128 + ty * 8 + 4);
            float4 b0 = *reinterpret_cast<const float4*>(Ks + dd * 128 + tx * 8);
            float4 b1 = *reinterpret_cast<const float4*>(Ks + dd * 128 + tx * 8 + 4);
            float ar[8] = {a0.x, a0.y, a0.z, a0.w, a1.x, a1.y, a1.z, a1.w};
            float br[8] = {b0.x, b0.y, b0.z, b0.w, b1.x, b1.y, b1.z, b1.w};
#pragma unroll
            for (int r = 0; r < 8; r++)
#pragma unroll
                for (int c = 0; c < 8; c++)
                    s[r][c] += ar[r] * br[c];
        }

        // ---- Online softmax over this chunk's 128 columns ----
        float fac[8];
#pragma unroll
        for (int r = 0; r < 8; r++) {
            float mx = s[r][0];
#pragma unroll
            for (int c = 1; c < 8; c++) mx = fmaxf(mx, s[r][c]);
#pragma unroll
            for (int off = 1; off < 16; off <<= 1)
                mx = fmaxf(mx, __shfl_xor_sync(0xffffffffu, mx, off));
            const float mn = fmaxf(m[r], mx);
            fac[r] = __expf(m[r] - mn);
            m[r] = mn;
            float ls = 0.f;
#pragma unroll
            for (int c = 0; c < 8; c++) {
                const float p = __expf(s[r][c] - mn);
                s[r][c] = p;
                ls += p;
            }
            l[r] = l[r] * fac[r] + ls;  // partial over this thread's 8 cols
        }

        // Stage P in smem
#pragma unroll
        for (int r = 0; r < 8; r++) {
            *reinterpret_cast<float4*>(Ps + (ty * 8 + r) * 132 + tx * 8) =
                make_float4(s[r][0], s[r][1], s[r][2], s[r][3]);
            *reinterpret_cast<float4*>(Ps + (ty * 8 + r) * 132 + tx * 8 + 4) =
                make_float4(s[r][4], s[r][5], s[r][6], s[r][7]);
        }
        __syncthreads();

        // ---- Phase B: O = O*fac + P @ V^T ----
#pragma unroll
        for (int r = 0; r < 8; r++)
#pragma unroll
            for (int c = 0; c < 4; c++) Oacc[r][c] *= fac[r];

#pragma unroll 2
        for (int jc = 0; jc < 128; jc += 4) {
            float4 vv[4];
#pragma unroll
            for (int u = 0; u < 4; u++)
                vv[u] = *reinterpret_cast<const float4*>(Vt + (jc + u) * 68 + tx * 4);
#pragma unroll
            for (int r = 0; r < 8; r++) {
                float4 pr = *reinterpret_cast<const float4*>(Ps + (ty * 8 + r) * 132 + jc);
                Oacc[r][0] += pr.x * vv[0].x + pr.y * vv[1].x + pr.z * vv[2].x + pr.w * vv[3].x;
                Oacc[r][1] += pr.x * vv[0].y + pr.y * vv[1].y + pr.z * vv[2].y + pr.w * vv[3].y;
                Oacc[r][2] += pr.x * vv[0].z + pr.y * vv[1].z + pr.z * vv[2].z + pr.w * vv[3].z;
                Oacc[r][3] += pr.x * vv[0].w + pr.y * vv[1].w + pr.z * vv[2].w + pr.w * vv[3].w;
            }
        }
    }

    // Final l reduction across the 16 tx lanes
    float inv[8];
#pragma unroll
    for (int r = 0; r < 8; r++) {
        float ls = l[r];
#pragma unroll
        for (int off = 1; off < 16; off <<= 1)
            ls += __shfl_xor_sync(0xffffffffu, ls, off);
        inv[r] = 1.f / ls;
    }

    // Stage O tile in smem (transpose to [dd][ic]) then coalesced store
    __syncthreads();
#pragma unroll
    for (int r = 0; r < 8; r++)
#pragma unroll
        for (int c = 0; c < 4; c++)
            Ps[(tx * 4 + c) * 132 + ty * 8 + r] = Oacc[r][c] * inv[r];
    __syncthreads();

#pragma unroll
    for (int it = 0; it < 8; it++) {
        int idx = tid * 4 + it * 1024;
        int dd = idx >> 7, ic = idx & 127;
        *reinterpret_cast<float4*>(Ob + (size_t)dd * HW + i0 + ic) =
            *reinterpret_cast<const float4*>(Ps + dd * 132 + ic);
    }
}

// ---------------------------------------------------------------------------
// Launch
// ---------------------------------------------------------------------------
extern "C" void kernel_launch(void* const* d_in, const int* in_sizes, int n_in,
                              void* d_out, int out_size)
{
    const float* x    = (const float*)d_in[0];   // [4,512,64,64]
    const float* wq   = (const float*)d_in[1];   // [512,512,1,1]
    const float* wkv  = (const float*)d_in[2];   // [1024,512,2,2]
    const float* wout = (const float*)d_in[3];   // [512,512,1,1]
    float* out = (float*)d_out;                  // [4,512,64,64]

    float *qbuf, *kvbuf, *obuf;
    cudaGetSymbolAddress((void**)&qbuf,  g_q);
    cudaGetSymbolAddress((void**)&kvbuf, g_kv);
    cudaGetSymbolAddress((void**)&obuf,  g_o);

    cudaFuncSetAttribute(attn_kernel,
                         cudaFuncAttributeMaxDynamicSharedMemorySize, ATTN_SMEM);

    // Q = Wq @ X   : M=512, N=4096, K=512, batched over 4
    sgemm_kernel<512, 4096, 512><<<dim3(32, 4, BATCH), 256>>>(wq, x, qbuf);

    // KV = Wkv @ im2col(X) : M=1024, N=1024, K=2048
    kv_gemm_kernel<<<dim3(8, 8, BATCH), 256>>>(wkv, x, kvbuf);

    // Fused attention (128 queries per CTA)
    attn_kernel<<<dim3(HW / 128, HEADS, BATCH), 256, ATTN_SMEM>>>(qbuf, kvbuf, obuf);

    // Y = Wout @ O
    sgemm_kernel<512, 4096, 512><<<dim3(32, 4, BATCH), 256>>>(wout, obuf, out);
}

// round 4
// speedup vs baseline: 4.9335x; 2.3861x over previous
#include <cuda_runtime.h>
#include <cstdint>

// Problem constants
#define BATCH 4
#define DIM   512
#define HEADS 8
#define DHEAD 64
#define HW    4096   // 64*64 query positions
#define LKV   1024   // 32*32 kv positions

// Scratch (device globals; allocation-free per harness rules)
__device__ float g_q [BATCH * DIM * HW];        // Q  [b][hd][s]
__device__ float g_kv[BATCH * 2 * DIM * LKV];   // KV [b][o][ij]
__device__ float g_o [BATCH * DIM * HW];        // attn out

// ---------------------------------------------------------------------------
// tf32 helpers
// ---------------------------------------------------------------------------
__device__ __forceinline__ uint32_t f2t(float f) {
    uint32_t u;
    asm("cvt.rna.tf32.f32 %0, %1;" : "=r"(u) : "f"(f));
    return u;
}

__device__ __forceinline__ void mma8(float& d0, float& d1, float& d2, float& d3,
                                     uint32_t a0, uint32_t a1, uint32_t a2, uint32_t a3,
                                     uint32_t b0, uint32_t b1) {
    asm("mma.sync.aligned.m16n8k8.row.col.f32.tf32.tf32.f32 "
        "{%0,%1,%2,%3},{%4,%5,%6,%7},{%8,%9},{%0,%1,%2,%3};"
        : "+f"(d0), "+f"(d1), "+f"(d2), "+f"(d3)
        : "r"(a0), "r"(a1), "r"(a2), "r"(a3), "r"(b0), "r"(b1));
}

// ---------------------------------------------------------------------------
// tf32 tensor-core GEMM:  C[b] = A @ B[b]
// A [M,K] row-major (weights, shared), B [K,N] row-major batched, C [M,N].
// CTA 128x128, BK=16. 128 threads = 4 warps, each a 64x64 warp tile
// (4 m-tiles x 8 n-tiles of m16n8k8). As stored [k][m], Bs [k][n], ld=136.
// ---------------------------------------------------------------------------
#define GLD 136

template <int M, int N, int K>
__global__ __launch_bounds__(128, 2)
void gemm_tf32(const float* __restrict__ A,
               const float* __restrict__ Bsrc,
               float* __restrict__ Csrc)
{
    __shared__ uint32_t As[16 * GLD];
    __shared__ uint32_t Bs[16 * GLD];

    const int tid  = threadIdx.x;
    const int lane = tid & 31;
    const int w    = tid >> 5;
    const int g    = lane >> 2;
    const int t    = lane & 3;
    const int m0w  = (w >> 1) * 64;
    const int n0w  = (w & 1) * 64;
    const int row0 = blockIdx.y * 128;
    const int col0 = blockIdx.x * 128;

    const float* Bp = Bsrc + (size_t)blockIdx.z * K * N;
    float*       Cp = Csrc + (size_t)blockIdx.z * M * N;

    const int ar = tid >> 1;          // 0..63 (+64)
    const int ac = (tid & 1) * 8;     // 0 or 8
    const int br = tid >> 5;          // 0..3 (+4*it)
    const int bc = (tid & 31) * 4;

    float acc[4][8][4];
#pragma unroll
    for (int mt = 0; mt < 4; mt++)
#pragma unroll
        for (int nt = 0; nt < 8; nt++)
#pragma unroll
            for (int r = 0; r < 4; r++) acc[mt][nt][r] = 0.f;

    for (int k0 = 0; k0 < K; k0 += 16) {
#pragma unroll
        for (int it = 0; it < 2; it++) {
            const float* ap = A + (size_t)(row0 + ar + it * 64) * K + k0 + ac;
            float4 v0 = *reinterpret_cast<const float4*>(ap);
            float4 v1 = *reinterpret_cast<const float4*>(ap + 4);
            const int m = ar + it * 64;
            As[(ac + 0) * GLD + m] = f2t(v0.x);
            As[(ac + 1) * GLD + m] = f2t(v0.y);
            As[(ac + 2) * GLD + m] = f2t(v0.z);
            As[(ac + 3) * GLD + m] = f2t(v0.w);
            As[(ac + 4) * GLD + m] = f2t(v1.x);
            As[(ac + 5) * GLD + m] = f2t(v1.y);
            As[(ac + 6) * GLD + m] = f2t(v1.z);
            As[(ac + 7) * GLD + m] = f2t(v1.w);
        }
#pragma unroll
        for (int it = 0; it < 4; it++) {
            float4 v = *reinterpret_cast<const float4*>(
                Bp + (size_t)(k0 + br + it * 4) * N + col0 + bc);
            uint4 u;
            u.x = f2t(v.x); u.y = f2t(v.y); u.z = f2t(v.z); u.w = f2t(v.w);
            *reinterpret_cast<uint4*>(&Bs[(br + it * 4) * GLD + bc]) = u;
        }
        __syncthreads();

#pragma unroll
        for (int s = 0; s < 2; s++) {
            uint32_t a[4][4], b[8][2];
#pragma unroll
            for (int mt = 0; mt < 4; mt++) {
                const uint32_t* p0 = &As[(s * 8 + t) * GLD + m0w + mt * 16 + g];
                const uint32_t* p1 = &As[(s * 8 + t + 4) * GLD + m0w + mt * 16 + g];
                a[mt][0] = p0[0]; a[mt][1] = p0[8];
                a[mt][2] = p1[0]; a[mt][3] = p1[8];
            }
#pragma unroll
            for (int nt = 0; nt < 8; nt++) {
                b[nt][0] = Bs[(s * 8 + t) * GLD + n0w + nt * 8 + g];
                b[nt][1] = Bs[(s * 8 + t + 4) * GLD + n0w + nt * 8 + g];
            }
#pragma unroll
            for (int mt = 0; mt < 4; mt++)
#pragma unroll
                for (int nt = 0; nt < 8; nt++)
                    mma8(acc[mt][nt][0], acc[mt][nt][1], acc[mt][nt][2], acc[mt][nt][3],
                         a[mt][0], a[mt][1], a[mt][2], a[mt][3],
                         b[nt][0], b[nt][1]);
        }
        __syncthreads();
    }

#pragma unroll
    for (int mt = 0; mt < 4; mt++)
#pragma unroll
        for (int nt = 0; nt < 8; nt++) {
            float* c0 = Cp + (size_t)(row0 + m0w + mt * 16 + g) * N
                           + col0 + n0w + nt * 8 + 2 * t;
            float2 v0; v0.x = acc[mt][nt][0]; v0.y = acc[mt][nt][1];
            float2 v1; v1.x = acc[mt][nt][2]; v1.y = acc[mt][nt][3];
            *reinterpret_cast<float2*>(c0)             = v0;
            *reinterpret_cast<float2*>(c0 + 8 * (size_t)N) = v1;
        }
}

// ---------------------------------------------------------------------------
// KV conv as implicit-im2col tf32 GEMM. Same tiling; B gathered from X.
// M=1024, N=1024, K=2048. k = c*4 + p*2 + q; n = i*32 + j.
// ---------------------------------------------------------------------------
__global__ __launch_bounds__(128, 2)
void kv_gemm_tf32(const float* __restrict__ Wkv,
                  const float* __restrict__ X,
                  float* __restrict__ KVout)
{
    constexpr int M = 1024, N = 1024, K = 2048;
    __shared__ uint32_t As[16 * GLD];
    __shared__ uint32_t Bs[16 * GLD];

    const int tid  = threadIdx.x;
    const int lane = tid & 31;
    const int w    = tid >> 5;
    const int g    = lane >> 2;
    const int t    = lane & 3;
    const int m0w  = (w >> 1) * 64;
    const int n0w  = (w & 1) * 64;
    const int row0 = blockIdx.y * 128;
    const int col0 = blockIdx.x * 128;

    const float* Xb = X + (size_t)blockIdx.z * DIM * HW;
    float*       Cp = KVout + (size_t)blockIdx.z * M * N;

    const int ar = tid >> 1;
    const int ac = (tid & 1) * 8;
    const int br = tid >> 5;
    const int bc = (tid & 31) * 4;

    float acc[4][8][4];
#pragma unroll
    for (int mt = 0; mt < 4; mt++)
#pragma unroll
        for (int nt = 0; nt < 8; nt++)
#pragma unroll
            for (int r = 0; r < 4; r++) acc[mt][nt][r] = 0.f;

    for (int k0 = 0; k0 < K; k0 += 16) {
#pragma unroll
        for (int it = 0; it < 2; it++) {
            const float* ap = Wkv + (size_t)(row0 + ar + it * 64) * K + k0 + ac;
            float4 v0 = *reinterpret_cast<const float4*>(ap);
            float4 v1 = *reinterpret_cast<const float4*>(ap + 4);
            const int m = ar + it * 64;
            As[(ac + 0) * GLD + m] = f2t(v0.x);
            As[(ac + 1) * GLD + m] = f2t(v0.y);
            As[(ac + 2) * GLD + m] = f2t(v0.z);
            As[(ac + 3) * GLD + m] = f2t(v0.w);
            As[(ac + 4) * GLD + m] = f2t(v1.x);
            As[(ac + 5) * GLD + m] = f2t(v1.y);
            As[(ac + 6) * GLD + m] = f2t(v1.z);
            As[(ac + 7) * GLD + m] = f2t(v1.w);
        }
#pragma unroll
        for (int it = 0; it < 4; it++) {
            const int krow = k0 + br + it * 4;
            const int c  = krow >> 2;
            const int p  = (krow >> 1) & 1;
            const int qq = krow & 1;
            const float* xr = Xb + (size_t)c * HW + p * 64 + qq;
            uint4 u;
            {
                int n = col0 + bc;
                u.x = f2t(xr[(n >> 5) * 128 + (n & 31) * 2]); n++;
                u.y = f2t(xr[(n >> 5) * 128 + (n & 31) * 2]); n++;
                u.z = f2t(xr[(n >> 5) * 128 + (n & 31) * 2]); n++;
                u.w = f2t(xr[(n >> 5) * 128 + (n & 31) * 2]);
            }
            *reinterpret_cast<uint4*>(&Bs[(br + it * 4) * GLD + bc]) = u;
        }
        __syncthreads();

#pragma unroll
        for (int s = 0; s < 2; s++) {
            uint32_t a[4][4], b[8][2];
#pragma unroll
            for (int mt = 0; mt < 4; mt++) {
                const uint32_t* p0 = &As[(s * 8 + t) * GLD + m0w + mt * 16 + g];
                const uint32_t* p1 = &As[(s * 8 + t + 4) * GLD + m0w + mt * 16 + g];
                a[mt][0] = p0[0]; a[mt][1] = p0[8];
                a[mt][2] = p1[0]; a[mt][3] = p1[8];
            }
#pragma unroll
            for (int nt = 0; nt < 8; nt++) {
                b[nt][0] = Bs[(s * 8 + t) * GLD + n0w + nt * 8 + g];
                b[nt][1] = Bs[(s * 8 + t + 4) * GLD + n0w + nt * 8 + g];
            }
#pragma unroll
            for (int mt = 0; mt < 4; mt++)
#pragma unroll
                for (int nt = 0; nt < 8; nt++)
                    mma8(acc[mt][nt][0], acc[mt][nt][1], acc[mt][nt][2], acc[mt][nt][3],
                         a[mt][0], a[mt][1], a[mt][2], a[mt][3],
                         b[nt][0], b[nt][1]);
        }
        __syncthreads();
    }

#pragma unroll
    for (int mt = 0; mt < 4; mt++)
#pragma unroll
        for (int nt = 0; nt < 8; nt++) {
            float* c0 = Cp + (size_t)(row0 + m0w + mt * 16 + g) * N
                           + col0 + n0w + nt * 8 + 2 * t;
            float2 v0; v0.x = acc[mt][nt][0]; v0.y = acc[mt][nt][1];
            float2 v1; v1.x = acc[mt][nt][2]; v1.y = acc[mt][nt][3];
            *reinterpret_cast<float2*>(c0)                 = v0;
            *reinterpret_cast<float2*>(c0 + 8 * (size_t)N) = v1;
        }
}

// ---------------------------------------------------------------------------
// Flash attention on tf32 tensor cores.
// CTA: 128 queries x 1 head, 128 threads (4 warps), key chunks of 128.
// Phase A: S = Q^T K, warp tile 32(i) x 128(j): full softmax row in-warp.
// P stored to per-warp-private smem rows as tf32 (no CTA sync needed).
// Phase B: O += P @ V^T, warp tile 32(i) x 64(d); V used directly as
// col-major B operand from its [d][j] layout (no transpose).
// Smem: Qs/Ks/Vs [64][136] u32 + Ps [128][136] = 170 KB.
// ---------------------------------------------------------------------------
#define ALD 136
#define ATTN_SMEM ((3 * 64 * ALD + 128 * ALD) * 4)

__global__ __launch_bounds__(128, 1)
void attn_tf32(const float* __restrict__ Q,
               const float* __restrict__ KV,
               float* __restrict__ Oout)
{
    const int bb = blockIdx.z;
    const int h  = blockIdx.y;
    const int i0 = blockIdx.x * 128;
    const int tid  = threadIdx.x;
    const int lane = tid & 31;
    const int w    = tid >> 5;
    const int g    = lane >> 2;
    const int t    = lane & 3;

    const float* Qb = Q  + ((size_t)bb * DIM + h * DHEAD) * HW;
    const float* Kb = KV + ((size_t)bb * 2 * DIM + h * DHEAD) * LKV;
    const float* Vb = KV + ((size_t)bb * 2 * DIM + DIM + h * DHEAD) * LKV;
    float*       Ob = Oout + ((size_t)bb * DIM + h * DHEAD) * HW;

    extern __shared__ uint32_t sm[];
    uint32_t* Qs = sm;               // [64][136]
    uint32_t* Ks = Qs + 64 * ALD;    // [64][136]
    uint32_t* Vs = Ks + 64 * ALD;    // [64][136]
    uint32_t* Ps = Vs + 64 * ALD;    // [128][136]
    float*    Pf = (float*)Ps;

    const int ldd = tid >> 5;        // 0..3
    const int ldc = (tid & 31) * 4;

    // Load Q tile (scaled by 0.125, tf32)
#pragma unroll
    for (int it = 0; it < 16; it++) {
        const int d = ldd + it * 4;
        float4 v = *reinterpret_cast<const float4*>(Qb + (size_t)d * HW + i0 + ldc);
        uint4 u;
        u.x = f2t(v.x * 0.125f); u.y = f2t(v.y * 0.125f);
        u.z = f2t(v.z * 0.125f); u.w = f2t(v.w * 0.125f);
        *reinterpret_cast<uint4*>(&Qs[d * ALD + ldc]) = u;
    }

    float o[2][8][4];
#pragma unroll
    for (int mt = 0; mt < 2; mt++)
#pragma unroll
        for (int nt = 0; nt < 8; nt++)
#pragma unroll
            for (int r = 0; r < 4; r++) o[mt][nt][r] = 0.f;

    float mrow[4], lrow[4];
#pragma unroll
    for (int r = 0; r < 4; r++) { mrow[r] = -1e30f; lrow[r] = 0.f; }

    for (int j0 = 0; j0 < LKV; j0 += 128) {
        __syncthreads();
#pragma unroll
        for (int it = 0; it < 16; it++) {
            const int d = ldd + it * 4;
            float4 kv4 = *reinterpret_cast<const float4*>(Kb + (size_t)d * LKV + j0 + ldc);
            uint4 uk;
            uk.x = f2t(kv4.x); uk.y = f2t(kv4.y); uk.z = f2t(kv4.z); uk.w = f2t(kv4.w);
            *reinterpret_cast<uint4*>(&Ks[d * ALD + ldc]) = uk;
            float4 vv4 = *reinterpret_cast<const float4*>(Vb + (size_t)d * LKV + j0 + ldc);
            uint4 uv;
            uv.x = f2t(vv4.x); uv.y = f2t(vv4.y); uv.z = f2t(vv4.z); uv.w = f2t(vv4.w);
            *reinterpret_cast<uint4*>(&Vs[d * ALD + ldc]) = uv;
        }
        __syncthreads();

        // ---- Phase A: S = Q^T K, warp tile 32x128 ----
        float s[2][16][4];
#pragma unroll
        for (int mt = 0; mt < 2; mt++)
#pragma unroll
            for (int nt = 0; nt < 16; nt++)
#pragma unroll
                for (int r = 0; r < 4; r++) s[mt][nt][r] = 0.f;

#pragma unroll
        for (int ks = 0; ks < 8; ks++) {
            uint32_t a[2][4];
#pragma unroll
            for (int mt = 0; mt < 2; mt++) {
                const uint32_t* p0 = &Qs[(ks * 8 + t) * ALD + 32 * w + mt * 16 + g];
                const uint32_t* p1 = &Qs[(ks * 8 + t + 4) * ALD + 32 * w + mt * 16 + g];
                a[mt][0] = p0[0]; a[mt][1] = p0[8];
                a[mt][2] = p1[0]; a[mt][3] = p1[8];
            }
#pragma unroll
            for (int nt = 0; nt < 16; nt++) {
                uint32_t b0 = Ks[(ks * 8 + t) * ALD + nt * 8 + g];
                uint32_t b1 = Ks[(ks * 8 + t + 4) * ALD + nt * 8 + g];
                mma8(s[0][nt][0], s[0][nt][1], s[0][nt][2], s[0][nt][3],
                     a[0][0], a[0][1], a[0][2], a[0][3], b0, b1);
                mma8(s[1][nt][0], s[1][nt][1], s[1][nt][2], s[1][nt][3],
                     a[1][0], a[1][1], a[1][2], a[1][3], b0, b1);
            }
        }

        // ---- Online softmax (rows live in the 4 t-lanes of each g-group) ----
        float fac[4];
#pragma unroll
        for (int mt = 0; mt < 2; mt++)
#pragma unroll
            for (int hh = 0; hh < 2; hh++) {
                const int idx = mt * 2 + hh;
                float mx = -1e30f;
#pragma unroll
                for (int nt = 0; nt < 16; nt++) {
                    mx = fmaxf(mx, s[mt][nt][2 * hh]);
                    mx = fmaxf(mx, s[mt][nt][2 * hh + 1]);
                }
                mx = fmaxf(mx, __shfl_xor_sync(0xffffffffu, mx, 1));
                mx = fmaxf(mx, __shfl_xor_sync(0xffffffffu, mx, 2));
                const float mn = fmaxf(mrow[idx], mx);
                fac[idx] = __expf(mrow[idx] - mn);
                mrow[idx] = mn;
                float ls = 0.f;
#pragma unroll
                for (int nt = 0; nt < 16; nt++) {
                    const float p0 = __expf(s[mt][nt][2 * hh]     - mn);
                    const float p1 = __expf(s[mt][nt][2 * hh + 1] - mn);
                    s[mt][nt][2 * hh]     = p0;
                    s[mt][nt][2 * hh + 1] = p1;
                    ls += p0 + p1;
                }
                lrow[idx] = lrow[idx] * fac[idx] + ls;
            }

        // Rescale O accumulators
#pragma unroll
        for (int mt = 0; mt < 2; mt++)
#pragma unroll
            for (int nt = 0; nt < 8; nt++) {
                o[mt][nt][0] *= fac[mt * 2];
                o[mt][nt][1] *= fac[mt * 2];
                o[mt][nt][2] *= fac[mt * 2 + 1];
                o[mt][nt][3] *= fac[mt * 2 + 1];
            }

        // Store P (tf32) to this warp's private rows of Ps
#pragma unroll
        for (int mt = 0; mt < 2; mt++) {
            const int row = 32 * w + mt * 16 + g;
#pragma unroll
            for (int nt = 0; nt < 16; nt++) {
                uint2 u0; u0.x = f2t(s[mt][nt][0]); u0.y = f2t(s[mt][nt][1]);
                uint2 u1; u1.x = f2t(s[mt][nt][2]); u1.y = f2t(s[mt][nt][3]);
                *reinterpret_cast<uint2*>(&Ps[row * ALD + nt * 8 + 2 * t])       = u0;
                *reinterpret_cast<uint2*>(&Ps[(row + 8) * ALD + nt * 8 + 2 * t]) = u1;
            }
        }
        __syncwarp();

        // ---- Phase B: O += P @ V^T, warp tile 32x64 ----
#pragma unroll
        for (int ks = 0; ks < 16; ks++) {
            uint32_t a[2][4];
#pragma unroll
            for (int mt = 0; mt < 2; mt++) {
                const uint32_t* p0 = &Ps[(32 * w + mt * 16 + g) * ALD + ks * 8 + t];
                const uint32_t* p1 = &Ps[(32 * w + mt * 16 + g + 8) * ALD + ks * 8 + t];
                a[mt][0] = p0[0]; a[mt][1] = p1[0];
                a[mt][2] = p0[4]; a[mt][3] = p1[4];
            }
#pragma unroll
            for (int nt = 0; nt < 8; nt++) {
                uint32_t b0 = Vs[(nt * 8 + g) * ALD + ks * 8 + t];
                uint32_t b1 = Vs[(nt * 8 + g) * ALD + ks * 8 + t + 4];
                mma8(o[0][nt][0], o[0][nt][1], o[0][nt][2], o[0][nt][3],
                     a[0][0], a[0][1], a[0][2], a[0][3], b0, b1);
                mma8(o[1][nt][0], o[1][nt][1], o[1][nt][2], o[1][nt][3],
                     a[1][0], a[1][1], a[1][2], a[1][3], b0, b1);
            }
        }
    }

    // Final l reduction across the 4 t-lanes
    float inv[4];
#pragma unroll
    for (int idx = 0; idx < 4; idx++) {
        float ls = lrow[idx];
        ls += __shfl_xor_sync(0xffffffffu, ls, 1);
        ls += __shfl_xor_sync(0xffffffffu, ls, 2);
        inv[idx] = 1.f / ls;
    }

    // Transpose O into smem as [d][i], then coalesced store
    __syncthreads();
#pragma unroll
    for (int mt = 0; mt < 2; mt++) {
        const int row = 32 * w + mt * 16 + g;
#pragma unroll
        for (int nt = 0; nt < 8; nt++) {
            const int d = nt * 8 + 2 * t;
            Pf[d * ALD + row]           = o[mt][nt][0] * inv[mt * 2];
            Pf[(d + 1) * ALD + row]     = o[mt][nt][1] * inv[mt * 2];
            Pf[d * ALD + row + 8]       = o[mt][nt][2] * inv[mt * 2 + 1];
            Pf[(d + 1) * ALD + row + 8] = o[mt][nt][3] * inv[mt * 2 + 1];
        }
    }
    __syncthreads();

#pragma unroll
    for (int it = 0; it < 16; it++) {
        const int d = ldd + it * 4;
        *reinterpret_cast<float4*>(Ob + (size_t)d * HW + i0 + ldc) =
            *reinterpret_cast<const float4*>(&Pf[d * ALD + ldc]);
    }
}

// ---------------------------------------------------------------------------
// Launch
// ---------------------------------------------------------------------------
extern "C" void kernel_launch(void* const* d_in, const int* in_sizes, int n_in,
                              void* d_out, int out_size)
{
    const float* x    = (const float*)d_in[0];   // [4,512,64,64]
    const float* wq   = (const float*)d_in[1];   // [512,512,1,1]
    const float* wkv  = (const float*)d_in[2];   // [1024,512,2,2]
    const float* wout = (const float*)d_in[3];   // [512,512,1,1]
    float* out = (float*)d_out;                  // [4,512,64,64]

    float *qbuf, *kvbuf, *obuf;
    cudaGetSymbolAddress((void**)&qbuf,  g_q);
    cudaGetSymbolAddress((void**)&kvbuf, g_kv);
    cudaGetSymbolAddress((void**)&obuf,  g_o);

    cudaFuncSetAttribute(attn_tf32,
                         cudaFuncAttributeMaxDynamicSharedMemorySize, ATTN_SMEM);

    // Q = Wq @ X : M=512, N=4096, K=512
    gemm_tf32<512, 4096, 512><<<dim3(32, 4, BATCH), 128>>>(wq, x, qbuf);

    // KV = Wkv @ im2col(X) : M=1024, N=1024, K=2048
    kv_gemm_tf32<<<dim3(8, 8, BATCH), 128>>>(wkv, x, kvbuf);

    // Fused attention
    attn_tf32<<<dim3(HW / 128, HEADS, BATCH), 128, ATTN_SMEM>>>(qbuf, kvbuf, obuf);

    // Y = Wout @ O
    gemm_tf32<512, 4096, 512><<<dim3(32, 4, BATCH), 128>>>(wout, obuf, out);
}

// round 5
// speedup vs baseline: 6.4391x; 1.3052x over previous
#include <cuda_runtime.h>
#include <cstdint>

// Problem constants
#define BATCH 4
#define DIM   512
#define HEADS 8
#define DHEAD 64
#define HW    4096   // 64*64 query positions
#define LKV   1024   // 32*32 kv positions

// Scratch (device globals; allocation-free per harness rules)
__device__ float g_q [BATCH * DIM * HW];        // Q  [b][hd][s]
__device__ float g_kv[BATCH * 2 * DIM * LKV];   // KV [b][o][ij]
__device__ float g_o [BATCH * DIM * HW];        // attn out

// ---------------------------------------------------------------------------
// tf32 helpers
// ---------------------------------------------------------------------------
__device__ __forceinline__ uint32_t f2t(float f) {
    uint32_t u;
    asm("cvt.rna.tf32.f32 %0, %1;" : "=r"(u) : "f"(f));
    return u;
}

__device__ __forceinline__ void mma8(float& d0, float& d1, float& d2, float& d3,
                                     uint32_t a0, uint32_t a1, uint32_t a2, uint32_t a3,
                                     uint32_t b0, uint32_t b1) {
    asm("mma.sync.aligned.m16n8k8.row.col.f32.tf32.tf32.f32 "
        "{%0,%1,%2,%3},{%4,%5,%6,%7},{%8,%9},{%0,%1,%2,%3};"
        : "+f"(d0), "+f"(d1), "+f"(d2), "+f"(d3)
        : "r"(a0), "r"(a1), "r"(a2), "r"(a3), "r"(b0), "r"(b1));
}

// ---------------------------------------------------------------------------
// tf32 tensor-core GEMM with double-buffered smem + register prefetch.
// C[b] = A @ B[b]; A [M,K] row-major shared; B [K,N] batched; C [M,N].
// CTA 128x128, BK=16, 4 warps x 64x64 warp tile. One sync per K-step.
// ---------------------------------------------------------------------------
#define GLD 136

template <int M, int N, int K>
__global__ __launch_bounds__(128, 2)
void gemm_tf32(const float* __restrict__ A,
               const float* __restrict__ Bsrc,
               float* __restrict__ Csrc)
{
    __shared__ uint32_t As[2][16 * GLD];
    __shared__ uint32_t Bs[2][16 * GLD];

    const int tid  = threadIdx.x;
    const int lane = tid & 31;
    const int w    = tid >> 5;
    const int g    = lane >> 2;
    const int t    = lane & 3;
    const int m0w  = (w >> 1) * 64;
    const int n0w  = (w & 1) * 64;
    const int row0 = blockIdx.y * 128;
    const int col0 = blockIdx.x * 128;

    const float* Bp = Bsrc + (size_t)blockIdx.z * K * N;
    float*       Cp = Csrc + (size_t)blockIdx.z * M * N;

    const int ar = tid >> 1;
    const int ac = (tid & 1) * 8;
    const int br = tid >> 5;
    const int bc = (tid & 31) * 4;

    float a_regs[16];
    float4 b_regs[4];

    auto LDG = [&](int k0) {
#pragma unroll
        for (int it = 0; it < 2; it++) {
            const float* ap = A + (size_t)(row0 + ar + it * 64) * K + k0 + ac;
            *reinterpret_cast<float4*>(&a_regs[it * 8])     = *reinterpret_cast<const float4*>(ap);
            *reinterpret_cast<float4*>(&a_regs[it * 8 + 4]) = *reinterpret_cast<const float4*>(ap + 4);
        }
#pragma unroll
        for (int it = 0; it < 4; it++)
            b_regs[it] = *reinterpret_cast<const float4*>(
                Bp + (size_t)(k0 + br + it * 4) * N + col0 + bc);
    };
    auto STS = [&](int buf) {
#pragma unroll
        for (int it = 0; it < 2; it++)
#pragma unroll
            for (int j = 0; j < 8; j++)
                As[buf][(ac + j) * GLD + ar + it * 64] = f2t(a_regs[it * 8 + j]);
#pragma unroll
        for (int it = 0; it < 4; it++) {
            uint4 u;
            u.x = f2t(b_regs[it].x); u.y = f2t(b_regs[it].y);
            u.z = f2t(b_regs[it].z); u.w = f2t(b_regs[it].w);
            *reinterpret_cast<uint4*>(&Bs[buf][(br + it * 4) * GLD + bc]) = u;
        }
    };

    float acc[4][8][4];
#pragma unroll
    for (int mt = 0; mt < 4; mt++)
#pragma unroll
        for (int nt = 0; nt < 8; nt++)
#pragma unroll
            for (int r = 0; r < 4; r++) acc[mt][nt][r] = 0.f;

    LDG(0);
    STS(0);
    __syncthreads();

    constexpr int NIT = K / 16;
    for (int i = 0; i < NIT; i++) {
        const int buf = i & 1;
        if (i + 1 < NIT) LDG((i + 1) * 16);

#pragma unroll
        for (int s = 0; s < 2; s++) {
            uint32_t a[4][4], b[8][2];
#pragma unroll
            for (int mt = 0; mt < 4; mt++) {
                const uint32_t* p0 = &As[buf][(s * 8 + t) * GLD + m0w + mt * 16 + g];
                const uint32_t* p1 = &As[buf][(s * 8 + t + 4) * GLD + m0w + mt * 16 + g];
                a[mt][0] = p0[0]; a[mt][1] = p0[8];
                a[mt][2] = p1[0]; a[mt][3] = p1[8];
            }
#pragma unroll
            for (int nt = 0; nt < 8; nt++) {
                b[nt][0] = Bs[buf][(s * 8 + t) * GLD + n0w + nt * 8 + g];
                b[nt][1] = Bs[buf][(s * 8 + t + 4) * GLD + n0w + nt * 8 + g];
            }
#pragma unroll
            for (int mt = 0; mt < 4; mt++)
#pragma unroll
                for (int nt = 0; nt < 8; nt++)
                    mma8(acc[mt][nt][0], acc[mt][nt][1], acc[mt][nt][2], acc[mt][nt][3],
                         a[mt][0], a[mt][1], a[mt][2], a[mt][3],
                         b[nt][0], b[nt][1]);
        }
        if (i + 1 < NIT) STS(buf ^ 1);
        __syncthreads();
    }

#pragma unroll
    for (int mt = 0; mt < 4; mt++)
#pragma unroll
        for (int nt = 0; nt < 8; nt++) {
            float* c0 = Cp + (size_t)(row0 + m0w + mt * 16 + g) * N
                           + col0 + n0w + nt * 8 + 2 * t;
            float2 v0; v0.x = acc[mt][nt][0]; v0.y = acc[mt][nt][1];
            float2 v1; v1.x = acc[mt][nt][2]; v1.y = acc[mt][nt][3];
            *reinterpret_cast<float2*>(c0)                 = v0;
            *reinterpret_cast<float2*>(c0 + 8 * (size_t)N) = v1;
        }
}

// ---------------------------------------------------------------------------
// KV conv as implicit-im2col tf32 GEMM, double-buffered like gemm_tf32.
// M=1024, N=1024, K=2048. k = c*4 + p*2 + q; n = i*32 + j.
// ---------------------------------------------------------------------------
__global__ __launch_bounds__(128, 2)
void kv_gemm_tf32(const float* __restrict__ Wkv,
                  const float* __restrict__ X,
                  float* __restrict__ KVout)
{
    constexpr int M = 1024, N = 1024, K = 2048;
    __shared__ uint32_t As[2][16 * GLD];
    __shared__ uint32_t Bs[2][16 * GLD];

    const int tid  = threadIdx.x;
    const int lane = tid & 31;
    const int w    = tid >> 5;
    const int g    = lane >> 2;
    const int t    = lane & 3;
    const int m0w  = (w >> 1) * 64;
    const int n0w  = (w & 1) * 64;
    const int row0 = blockIdx.y * 128;
    const int col0 = blockIdx.x * 128;

    const float* Xb = X + (size_t)blockIdx.z * DIM * HW;
    float*       Cp = KVout + (size_t)blockIdx.z * M * N;

    const int ar = tid >> 1;
    const int ac = (tid & 1) * 8;
    const int br = tid >> 5;
    const int bc = (tid & 31) * 4;

    float a_regs[16];
    float b_regs[4][4];

    auto LDG = [&](int k0) {
#pragma unroll
        for (int it = 0; it < 2; it++) {
            const float* ap = Wkv + (size_t)(row0 + ar + it * 64) * K + k0 + ac;
            *reinterpret_cast<float4*>(&a_regs[it * 8])     = *reinterpret_cast<const float4*>(ap);
            *reinterpret_cast<float4*>(&a_regs[it * 8 + 4]) = *reinterpret_cast<const float4*>(ap + 4);
        }
#pragma unroll
        for (int it = 0; it < 4; it++) {
            const int krow = k0 + br + it * 4;
            const int c  = krow >> 2;
            const int p  = (krow >> 1) & 1;
            const int qq = krow & 1;
            const float* xr = Xb + (size_t)c * HW + p * 64 + qq;
#pragma unroll
            for (int u = 0; u < 4; u++) {
                const int n = col0 + bc + u;
                b_regs[it][u] = xr[(n >> 5) * 128 + (n & 31) * 2];
            }
        }
    };
    auto STS = [&](int buf) {
#pragma unroll
        for (int it = 0; it < 2; it++)
#pragma unroll
            for (int j = 0; j < 8; j++)
                As[buf][(ac + j) * GLD + ar + it * 64] = f2t(a_regs[it * 8 + j]);
#pragma unroll
        for (int it = 0; it < 4; it++) {
            uint4 u;
            u.x = f2t(b_regs[it][0]); u.y = f2t(b_regs[it][1]);
            u.z = f2t(b_regs[it][2]); u.w = f2t(b_regs[it][3]);
            *reinterpret_cast<uint4*>(&Bs[buf][(br + it * 4) * GLD + bc]) = u;
        }
    };

    float acc[4][8][4];
#pragma unroll
    for (int mt = 0; mt < 4; mt++)
#pragma unroll
        for (int nt = 0; nt < 8; nt++)
#pragma unroll
            for (int r = 0; r < 4; r++) acc[mt][nt][r] = 0.f;

    LDG(0);
    STS(0);
    __syncthreads();

    constexpr int NIT = K / 16;
    for (int i = 0; i < NIT; i++) {
        const int buf = i & 1;
        if (i + 1 < NIT) LDG((i + 1) * 16);

#pragma unroll
        for (int s = 0; s < 2; s++) {
            uint32_t a[4][4], b[8][2];
#pragma unroll
            for (int mt = 0; mt < 4; mt++) {
                const uint32_t* p0 = &As[buf][(s * 8 + t) * GLD + m0w + mt * 16 + g];
                const uint32_t* p1 = &As[buf][(s * 8 + t + 4) * GLD + m0w + mt * 16 + g];
                a[mt][0] = p0[0]; a[mt][1] = p0[8];
                a[mt][2] = p1[0]; a[mt][3] = p1[8];
            }
#pragma unroll
            for (int nt = 0; nt < 8; nt++) {
                b[nt][0] = Bs[buf][(s * 8 + t) * GLD + n0w + nt * 8 + g];
                b[nt][1] = Bs[buf][(s * 8 + t + 4) * GLD + n0w + nt * 8 + g];
            }
#pragma unroll
            for (int mt = 0; mt < 4; mt++)
#pragma unroll
                for (int nt = 0; nt < 8; nt++)
                    mma8(acc[mt][nt][0], acc[mt][nt][1], acc[mt][nt][2], acc[mt][nt][3],
                         a[mt][0], a[mt][1], a[mt][2], a[mt][3],
                         b[nt][0], b[nt][1]);
        }
        if (i + 1 < NIT) STS(buf ^ 1);
        __syncthreads();
    }

#pragma unroll
    for (int mt = 0; mt < 4; mt++)
#pragma unroll
        for (int nt = 0; nt < 8; nt++) {
            float* c0 = Cp + (size_t)(row0 + m0w + mt * 16 + g) * N
                           + col0 + n0w + nt * 8 + 2 * t;
            float2 v0; v0.x = acc[mt][nt][0]; v0.y = acc[mt][nt][1];
            float2 v1; v1.x = acc[mt][nt][2]; v1.y = acc[mt][nt][3];
            *reinterpret_cast<float2*>(c0)                 = v0;
            *reinterpret_cast<float2*>(c0 + 8 * (size_t)N) = v1;
        }
}

// ---------------------------------------------------------------------------
// Flash attention on tf32 tensor cores, register-resident P.
// CTA: 128 queries x 1 head, 128 threads (4 warps), key chunks of 128.
// Phase A computes S with K columns permuted by pi(n) = (n&1)*4 + (n>>1),
// which makes the S accumulator fragment directly usable as the phase-B
// A-operand fragment (no smem staging of P). Smem: Qs/Ks/Vs only -> 104 KB,
// 2 CTAs/SM.
// ---------------------------------------------------------------------------
#define ALD 136
#define ATTN_SMEM (3 * 64 * ALD * 4)

__global__ __launch_bounds__(128, 2)
void attn_tf32(const float* __restrict__ Q,
               const float* __restrict__ KV,
               float* __restrict__ Oout)
{
    const int bb = blockIdx.z;
    const int h  = blockIdx.y;
    const int i0 = blockIdx.x * 128;
    const int tid  = threadIdx.x;
    const int lane = tid & 31;
    const int w    = tid >> 5;
    const int g    = lane >> 2;
    const int t    = lane & 3;
    const int pg   = (g & 1) * 4 + (g >> 1);   // pi(g) column permutation

    const float* Qb = Q  + ((size_t)bb * DIM + h * DHEAD) * HW;
    const float* Kb = KV + ((size_t)bb * 2 * DIM + h * DHEAD) * LKV;
    const float* Vb = KV + ((size_t)bb * 2 * DIM + DIM + h * DHEAD) * LKV;
    float*       Ob = Oout + ((size_t)bb * DIM + h * DHEAD) * HW;

    extern __shared__ uint32_t sm[];
    uint32_t* Qs = sm;               // [64][136]
    uint32_t* Ks = Qs + 64 * ALD;    // [64][136]
    uint32_t* Vs = Ks + 64 * ALD;    // [64][136]

    const int ldd = tid >> 5;
    const int ldc = (tid & 31) * 4;

    // Load Q tile (scaled by 0.125, tf32)
#pragma unroll
    for (int it = 0; it < 16; it++) {
        const int d = ldd + it * 4;
        float4 v = *reinterpret_cast<const float4*>(Qb + (size_t)d * HW + i0 + ldc);
        uint4 u;
        u.x = f2t(v.x * 0.125f); u.y = f2t(v.y * 0.125f);
        u.z = f2t(v.z * 0.125f); u.w = f2t(v.w * 0.125f);
        *reinterpret_cast<uint4*>(&Qs[d * ALD + ldc]) = u;
    }

    float o[2][8][4];
#pragma unroll
    for (int mt = 0; mt < 2; mt++)
#pragma unroll
        for (int nt = 0; nt < 8; nt++)
#pragma unroll
            for (int r = 0; r < 4; r++) o[mt][nt][r] = 0.f;

    float mrow[4], lrow[4];
#pragma unroll
    for (int r = 0; r < 4; r++) { mrow[r] = -1e30f; lrow[r] = 0.f; }

    for (int j0 = 0; j0 < LKV; j0 += 128) {
        __syncthreads();
#pragma unroll
        for (int it = 0; it < 16; it++) {
            const int d = ldd + it * 4;
            float4 kv4 = *reinterpret_cast<const float4*>(Kb + (size_t)d * LKV + j0 + ldc);
            uint4 uk;
            uk.x = f2t(kv4.x); uk.y = f2t(kv4.y); uk.z = f2t(kv4.z); uk.w = f2t(kv4.w);
            *reinterpret_cast<uint4*>(&Ks[d * ALD + ldc]) = uk;
            float4 vv4 = *reinterpret_cast<const float4*>(Vb + (size_t)d * LKV + j0 + ldc);
            uint4 uv;
            uv.x = f2t(vv4.x); uv.y = f2t(vv4.y); uv.z = f2t(vv4.z); uv.w = f2t(vv4.w);
            *reinterpret_cast<uint4*>(&Vs[d * ALD + ldc]) = uv;
        }
        __syncthreads();

        // ---- Phase A: S = Q^T K (K columns permuted by pi) ----
        float s[2][16][4];
#pragma unroll
        for (int mt = 0; mt < 2; mt++)
#pragma unroll
            for (int nt = 0; nt < 16; nt++)
#pragma unroll
                for (int r = 0; r < 4; r++) s[mt][nt][r] = 0.f;

#pragma unroll
        for (int ks = 0; ks < 8; ks++) {
            uint32_t a[2][4];
#pragma unroll
            for (int mt = 0; mt < 2; mt++) {
                const uint32_t* p0 = &Qs[(ks * 8 + t) * ALD + 32 * w + mt * 16 + g];
                const uint32_t* p1 = &Qs[(ks * 8 + t + 4) * ALD + 32 * w + mt * 16 + g];
                a[mt][0] = p0[0]; a[mt][1] = p0[8];
                a[mt][2] = p1[0]; a[mt][3] = p1[8];
            }
#pragma unroll
            for (int nt = 0; nt < 16; nt++) {
                uint32_t b0 = Ks[(ks * 8 + t) * ALD + nt * 8 + pg];
                uint32_t b1 = Ks[(ks * 8 + t + 4) * ALD + nt * 8 + pg];
                mma8(s[0][nt][0], s[0][nt][1], s[0][nt][2], s[0][nt][3],
                     a[0][0], a[0][1], a[0][2], a[0][3], b0, b1);
                mma8(s[1][nt][0], s[1][nt][1], s[1][nt][2], s[1][nt][3],
                     a[1][0], a[1][1], a[1][2], a[1][3], b0, b1);
            }
        }

        // ---- Online softmax (regs {0,1}=row g, {2,3}=row g+8) ----
        float fac[4];
#pragma unroll
        for (int mt = 0; mt < 2; mt++)
#pragma unroll
            for (int hh = 0; hh < 2; hh++) {
                const int idx = mt * 2 + hh;
                float mx = -1e30f;
#pragma unroll
                for (int nt = 0; nt < 16; nt++) {
                    mx = fmaxf(mx, s[mt][nt][2 * hh]);
                    mx = fmaxf(mx, s[mt][nt][2 * hh + 1]);
                }
                mx = fmaxf(mx, __shfl_xor_sync(0xffffffffu, mx, 1));
                mx = fmaxf(mx, __shfl_xor_sync(0xffffffffu, mx, 2));
                const float mn = fmaxf(mrow[idx], mx);
                fac[idx] = __expf(mrow[idx] - mn);
                mrow[idx] = mn;
                float ls = 0.f;
#pragma unroll
                for (int nt = 0; nt < 16; nt++) {
                    const float p0 = __expf(s[mt][nt][2 * hh]     - mn);
                    const float p1 = __expf(s[mt][nt][2 * hh + 1] - mn);
                    s[mt][nt][2 * hh]     = p0;
                    s[mt][nt][2 * hh + 1] = p1;
                    ls += p0 + p1;
                }
                lrow[idx] = lrow[idx] * fac[idx] + ls;
            }

        // Rescale O accumulators
#pragma unroll
        for (int mt = 0; mt < 2; mt++)
#pragma unroll
            for (int nt = 0; nt < 8; nt++) {
                o[mt][nt][0] *= fac[mt * 2];
                o[mt][nt][1] *= fac[mt * 2];
                o[mt][nt][2] *= fac[mt * 2 + 1];
                o[mt][nt][3] *= fac[mt * 2 + 1];
            }

        // Convert P to tf32 in registers
#pragma unroll
        for (int mt = 0; mt < 2; mt++)
#pragma unroll
            for (int nt = 0; nt < 16; nt++)
#pragma unroll
                for (int r = 0; r < 4; r++)
                    s[mt][nt][r] = __uint_as_float(f2t(s[mt][nt][r]));

        // ---- Phase B: O += P @ V^T (P from registers) ----
#pragma unroll
        for (int ks = 0; ks < 16; ks++) {
            uint32_t a[2][4];
#pragma unroll
            for (int mt = 0; mt < 2; mt++) {
                a[mt][0] = __float_as_uint(s[mt][ks][0]);
                a[mt][1] = __float_as_uint(s[mt][ks][2]);
                a[mt][2] = __float_as_uint(s[mt][ks][1]);
                a[mt][3] = __float_as_uint(s[mt][ks][3]);
            }
#pragma unroll
            for (int nt = 0; nt < 8; nt++) {
                uint32_t b0 = Vs[(nt * 8 + g) * ALD + ks * 8 + t];
                uint32_t b1 = Vs[(nt * 8 + g) * ALD + ks * 8 + t + 4];
                mma8(o[0][nt][0], o[0][nt][1], o[0][nt][2], o[0][nt][3],
                     a[0][0], a[0][1], a[0][2], a[0][3], b0, b1);
                mma8(o[1][nt][0], o[1][nt][1], o[1][nt][2], o[1][nt][3],
                     a[1][0], a[1][1], a[1][2], a[1][3], b0, b1);
            }
        }
    }

    // Final l reduction across the 4 t-lanes
    float inv[4];
#pragma unroll
    for (int idx = 0; idx < 4; idx++) {
        float ls = lrow[idx];
        ls += __shfl_xor_sync(0xffffffffu, ls, 1);
        ls += __shfl_xor_sync(0xffffffffu, ls, 2);
        inv[idx] = 1.f / ls;
    }

    // Stage O^T [d][i] in smem (reuse Qs region), then coalesced store
    __syncthreads();
    float* Of = reinterpret_cast<float*>(Qs);
#pragma unroll
    for (int mt = 0; mt < 2; mt++) {
        const int row = 32 * w + mt * 16 + g;
#pragma unroll
        for (int nt = 0; nt < 8; nt++) {
            const int d = nt * 8 + 2 * t;
            Of[d * ALD + row]           = o[mt][nt][0] * inv[mt * 2];
            Of[(d + 1) * ALD + row]     = o[mt][nt][1] * inv[mt * 2];
            Of[d * ALD + row + 8]       = o[mt][nt][2] * inv[mt * 2 + 1];
            Of[(d + 1) * ALD + row + 8] = o[mt][nt][3] * inv[mt * 2 + 1];
        }
    }
    __syncthreads();

#pragma unroll
    for (int it = 0; it < 16; it++) {
        const int d = ldd + it * 4;
        *reinterpret_cast<float4*>(Ob + (size_t)d * HW + i0 + ldc) =
            *reinterpret_cast<const float4*>(&Of[d * ALD + ldc]);
    }
}

// ---------------------------------------------------------------------------
// Launch
// ---------------------------------------------------------------------------
extern "C" void kernel_launch(void* const* d_in, const int* in_sizes, int n_in,
                              void* d_out, int out_size)
{
    const float* x    = (const float*)d_in[0];   // [4,512,64,64]
    const float* wq   = (const float*)d_in[1];   // [512,512,1,1]
    const float* wkv  = (const float*)d_in[2];   // [1024,512,2,2]
    const float* wout = (const float*)d_in[3];   // [512,512,1,1]
    float* out = (float*)d_out;                  // [4,512,64,64]

    float *qbuf, *kvbuf, *obuf;
    cudaGetSymbolAddress((void**)&qbuf,  g_q);
    cudaGetSymbolAddress((void**)&kvbuf, g_kv);
    cudaGetSymbolAddress((void**)&obuf,  g_o);

    cudaFuncSetAttribute(attn_tf32,
                         cudaFuncAttributeMaxDynamicSharedMemorySize, ATTN_SMEM);

    // Q = Wq @ X : M=512, N=4096, K=512
    gemm_tf32<512, 4096, 512><<<dim3(32, 4, BATCH), 128>>>(wq, x, qbuf);

    // KV = Wkv @ im2col(X) : M=1024, N=1024, K=2048
    kv_gemm_tf32<<<dim3(8, 8, BATCH), 128>>>(wkv, x, kvbuf);

    // Fused attention
    attn_tf32<<<dim3(HW / 128, HEADS, BATCH), 128, ATTN_SMEM>>>(qbuf, kvbuf, obuf);

    // Y = Wout @ O
    gemm_tf32<512, 4096, 512><<<dim3(32, 4, BATCH), 128>>>(wout, obuf, out);
}